// round 12
// baseline (speedup 1.0000x reference)
#include <cuda_runtime.h>
#include <cuda_bf16.h>

typedef unsigned int u32;
typedef unsigned long long u64;

// ---------------------------------------------------------------------------
// VAE_Gumbel R12: B-fragment pipelining, BN fused into wc_w2 staging,
// fused mean/logvar head, warp-reduce topk, spmm unroll 8.
// B=4096, D=5000, H=512, Z=64.
// ---------------------------------------------------------------------------

#define SPCAP 2048
enum { EPI_NONE = 0, EPI_LEAKY = 2, EPI_SIGMOID = 3 };

#define AST 72    // A smem row stride (bf16)
#define BST 136   // B smem row stride (bf16)

__device__ __forceinline__ u32 smem_u32(const void* p) {
    u32 a;
    asm("{ .reg .u64 t; cvta.to.shared.u64 t, %1; cvt.u32.u64 %0, t; }"
        : "=r"(a) : "l"(p));
    return a;
}

__device__ __forceinline__ void ldsm_x4(u32& r0, u32& r1, u32& r2, u32& r3, u32 addr) {
    asm volatile("ldmatrix.sync.aligned.m8n8.x4.shared.b16 {%0,%1,%2,%3}, [%4];"
                 : "=r"(r0), "=r"(r1), "=r"(r2), "=r"(r3) : "r"(addr));
}
__device__ __forceinline__ void ldsm_x4t(u32& r0, u32& r1, u32& r2, u32& r3, u32 addr) {
    asm volatile("ldmatrix.sync.aligned.m8n8.x4.trans.shared.b16 {%0,%1,%2,%3}, [%4];"
                 : "=r"(r0), "=r"(r1), "=r"(r2), "=r"(r3) : "r"(addr));
}
__device__ __forceinline__ void mma_bf16(float* d, const u32* a, u32 b0, u32 b1) {
    asm volatile("mma.sync.aligned.m16n8k16.row.col.f32.bf16.bf16.f32 "
                 "{%0,%1,%2,%3}, {%4,%5,%6,%7}, {%8,%9}, {%0,%1,%2,%3};"
                 : "+f"(d[0]), "+f"(d[1]), "+f"(d[2]), "+f"(d[3])
                 : "r"(a[0]), "r"(a[1]), "r"(a[2]), "r"(a[3]), "r"(b0), "r"(b1));
}

__device__ __forceinline__ u64 pack4bf(float v0, float v1, float v2, float v3,
                                       u64& lo_out) {
    __nv_bfloat16 h0 = __float2bfloat16(v0);
    __nv_bfloat16 h1 = __float2bfloat16(v1);
    __nv_bfloat16 h2 = __float2bfloat16(v2);
    __nv_bfloat16 h3 = __float2bfloat16(v3);
    __nv_bfloat16 l0 = __float2bfloat16(v0 - __bfloat162float(h0));
    __nv_bfloat16 l1 = __float2bfloat16(v1 - __bfloat162float(h1));
    __nv_bfloat16 l2 = __float2bfloat16(v2 - __bfloat162float(h2));
    __nv_bfloat16 l3 = __float2bfloat16(v3 - __bfloat162float(h3));
    lo_out = (u64)*(unsigned short*)&l0 | ((u64)*(unsigned short*)&l1 << 16)
           | ((u64)*(unsigned short*)&l2 << 32) | ((u64)*(unsigned short*)&l3 << 48);
    return (u64)*(unsigned short*)&h0 | ((u64)*(unsigned short*)&h1 << 16)
         | ((u64)*(unsigned short*)&h2 << 32) | ((u64)*(unsigned short*)&h3 << 48);
}

// ---------------------------------------------------------------------------
// bf16x3 split tensor-core GEMM: C[M,N] = act(A'[M,K] @ B[K,N] + bias)
// A' = PREBN ? relu((A-mean)*rstd*g + b) : A  (fused BatchNorm on A columns)
// Tile 128x128, K chunk 64, 8 warps (4x2), warp tile 32x64.
// ---------------------------------------------------------------------------
template <int EPI, int PREBN>
__global__ __launch_bounds__(256, 2)
void mma_gemm(const float* __restrict__ A, const float* __restrict__ B,
              const float* __restrict__ bias, float* __restrict__ C,
              int M, int N, int K,
              const float* __restrict__ bnm, const float* __restrict__ bnr,
              const float* __restrict__ bng, const float* __restrict__ bnb)
{
    extern __shared__ __nv_bfloat16 smem[];
    __nv_bfloat16* Ash_h = smem;                       // [128][AST]
    __nv_bfloat16* Ash_l = Ash_h + 128 * AST;
    __nv_bfloat16* Bsh_h = Ash_l + 128 * AST;          // [64][BST]
    __nv_bfloat16* Bsh_l = Bsh_h + 64 * BST;

    const int tid = threadIdx.x, lane = tid & 31, wid = tid >> 5;
    const int wm = (wid & 3) * 32;
    const int wn = (wid >> 2) * 64;
    const int row0 = blockIdx.y * 128, n0 = blockIdx.x * 128;

    const u32 aBase = smem_u32(Ash_h);
    const u32 alBase = smem_u32(Ash_l);
    const u32 bBase = smem_u32(Bsh_h);
    const u32 blBase = smem_u32(Bsh_l);

    float acc[2][8][4];
#pragma unroll
    for (int i = 0; i < 2; i++)
#pragma unroll
        for (int j = 0; j < 8; j++)
#pragma unroll
            for (int q = 0; q < 4; q++) acc[i][j][q] = 0.f;

    const int ar = tid >> 1;
    const int ak = (tid & 1) * 4;
    const int bk = tid >> 2;
    const int bn = (tid & 3) * 4;

    const int lm15 = lane & 15;
    const int lm16 = (lane >> 4) * 8;

    const int nchunks = (K + 63) / 64;
    for (int ch = 0; ch < nchunks; ch++) {
        const int k0 = ch * 64;
        __syncthreads();

        // ---- stage A [128 x 64] hi/lo (optional fused BN+ReLU) ----
        {
            const float* Ap = A + (size_t)(row0 + ar) * K + k0 + ak;
#pragma unroll
            for (int j = 0; j < 8; j++) {
                const int koff = ak + 8 * j;
                const int kk = k0 + koff;
                float4 v = (kk < K) ? *(const float4*)(Ap + 8 * j)
                                    : make_float4(0.f, 0.f, 0.f, 0.f);
                if (PREBN && kk < K) {
                    float4 mn = *(const float4*)(bnm + kk);
                    float4 rs = *(const float4*)(bnr + kk);
                    float4 gg = *(const float4*)(bng + kk);
                    float4 bb = *(const float4*)(bnb + kk);
                    v.x = fmaxf((v.x - mn.x) * rs.x * gg.x + bb.x, 0.f);
                    v.y = fmaxf((v.y - mn.y) * rs.y * gg.y + bb.y, 0.f);
                    v.z = fmaxf((v.z - mn.z) * rs.z * gg.z + bb.z, 0.f);
                    v.w = fmaxf((v.w - mn.w) * rs.w * gg.w + bb.w, 0.f);
                }
                u64 lo;
                u64 hi = pack4bf(v.x, v.y, v.z, v.w, lo);
                const int off = ar * AST + koff;
                *(u64*)(Ash_h + off) = hi;
                *(u64*)(Ash_l + off) = lo;
            }
        }
        // ---- stage B [64 x 128] hi/lo ----
        {
            const float* Bp = B + (size_t)(k0 + bk) * N + n0 + bn;
            const bool kval = (k0 + bk) < K;
#pragma unroll
            for (int j = 0; j < 8; j++) {
                const int noff = bn + 16 * j;
                float4 v = (kval && (n0 + noff) < N) ? *(const float4*)(Bp + 16 * j)
                                                     : make_float4(0.f, 0.f, 0.f, 0.f);
                u64 lo;
                u64 hi = pack4bf(v.x, v.y, v.z, v.w, lo);
                const int off = bk * BST + noff;
                *(u64*)(Bsh_h + off) = hi;
                *(u64*)(Bsh_l + off) = lo;
            }
        }
        __syncthreads();

        // ---- 4 x k16 MMA steps; B fragments pipelined across np ----
#pragma unroll
        for (int ks = 0; ks < 4; ks++) {
            u32 afh[2][4], afl[2][4];
#pragma unroll
            for (int mi = 0; mi < 2; mi++) {
                const u32 aoff = (u32)((wm + mi * 16 + lm15) * AST + ks * 16 + lm16) * 2;
                ldsm_x4(afh[mi][0], afh[mi][1], afh[mi][2], afh[mi][3], aBase + aoff);
                ldsm_x4(afl[mi][0], afl[mi][1], afl[mi][2], afl[mi][3], alBase + aoff);
            }
            u32 bh[4], bl[4];     // current np fragments (2 n8 tiles hi + lo)
            {
                const u32 boff = (u32)((ks * 16 + lm15) * BST + wn + lm16) * 2;
                ldsm_x4t(bh[0], bh[1], bh[2], bh[3], bBase + boff);
                ldsm_x4t(bl[0], bl[1], bl[2], bl[3], blBase + boff);
            }
#pragma unroll
            for (int np = 0; np < 4; np++) {
                u32 nh[4], nl[4];
                if (np < 3) {
                    const u32 boff = (u32)((ks * 16 + lm15) * BST + wn + (np + 1) * 16 + lm16) * 2;
                    ldsm_x4t(nh[0], nh[1], nh[2], nh[3], bBase + boff);
                    ldsm_x4t(nl[0], nl[1], nl[2], nl[3], blBase + boff);
                }
#pragma unroll
                for (int mi = 0; mi < 2; mi++) {
                    mma_bf16(acc[mi][2 * np],     afh[mi], bh[0], bh[1]);
                    mma_bf16(acc[mi][2 * np],     afh[mi], bl[0], bl[1]);
                    mma_bf16(acc[mi][2 * np],     afl[mi], bh[0], bh[1]);
                    mma_bf16(acc[mi][2 * np + 1], afh[mi], bh[2], bh[3]);
                    mma_bf16(acc[mi][2 * np + 1], afh[mi], bl[2], bl[3]);
                    mma_bf16(acc[mi][2 * np + 1], afl[mi], bh[2], bh[3]);
                }
                if (np < 3) {
#pragma unroll
                    for (int q = 0; q < 4; q++) { bh[q] = nh[q]; bl[q] = nl[q]; }
                }
            }
        }
    }

    // ---- epilogue ----
    const int rg = lane >> 2;
    const int cp = (lane & 3) * 2;
#pragma unroll
    for (int mi = 0; mi < 2; mi++) {
#pragma unroll
        for (int ni = 0; ni < 8; ni++) {
            const int c = n0 + wn + ni * 8 + cp;
            if (c < N) {
                const float b0 = bias[c], b1 = bias[c + 1];
#pragma unroll
                for (int half = 0; half < 2; half++) {
                    const int r = row0 + wm + mi * 16 + rg + half * 8;
                    float v0 = acc[mi][ni][2 * half]     + b0;
                    float v1 = acc[mi][ni][2 * half + 1] + b1;
                    if (EPI == EPI_LEAKY) {
                        v0 = v0 > 0.f ? v0 : 0.01f * v0;
                        v1 = v1 > 0.f ? v1 : 0.01f * v1;
                    }
                    if (EPI == EPI_SIGMOID) {
                        v0 = 1.0f / (1.0f + __expf(-v0));
                        v1 = 1.0f / (1.0f + __expf(-v1));
                    }
                    C[(size_t)r * N + c]     = v0;
                    C[(size_t)r * N + c + 1] = v1;
                }
            }
        }
    }
}

#define MMA_SMEM ((2 * 128 * AST + 2 * 64 * BST) * (int)sizeof(__nv_bfloat16))

// ---------------------------------------------------------------------------
// Scratch globals
// ---------------------------------------------------------------------------
__device__ float g_h   [4096u * 512];
__device__ float g_w   [4096u * 5000];
__device__ float g_h1  [4096u * 1024];
__device__ float g_h2  [4096u * 512];
__device__ float g_h3  [4096u * 512];
__device__ float g_z   [4096u * 64];
__device__ float g_dh  [4096u * 1024];
__device__ float g_mean[512];
__device__ float g_rstd[512];
__device__ float g_wcat[512u * 128];
__device__ float g_bcat[128];
__device__ float g_zcat[4096u * 128];
__device__ float g_spv [4096u * SPCAP];
__device__ int   g_spi [4096u * SPCAP];
__device__ int   g_spc [4096];

// ---------------------------------------------------------------------------
__global__ void bn_stats_kernel(const float* __restrict__ h,
                                float* __restrict__ mean, float* __restrict__ rstd)
{
    const int col = blockIdx.x * 32 + threadIdx.x;
    float s = 0.f, s2 = 0.f;
    for (int r = threadIdx.y; r < 4096; r += 8) {
        float v = h[(size_t)r * 512 + col];
        s += v; s2 += v * v;
    }
    __shared__ float sh[8][32];
    __shared__ float sh2[8][32];
    sh[threadIdx.y][threadIdx.x]  = s;
    sh2[threadIdx.y][threadIdx.x] = s2;
    __syncthreads();
    if (threadIdx.y == 0) {
        for (int y = 1; y < 8; y++) { s += sh[y][threadIdx.x]; s2 += sh2[y][threadIdx.x]; }
        float m   = s * (1.f / 4096.f);
        float var = s2 * (1.f / 4096.f) - m * m;
        mean[col] = m;
        rstd[col] = rsqrtf(var + 1e-5f);
    }
}

// concat mean/logvar heads: wcat[k][0:64]=m_w[k], wcat[k][64:128]=lv_w[k]
__global__ void concat_head_kernel(const float* __restrict__ mw, const float* __restrict__ lw,
                                   const float* __restrict__ mb, const float* __restrict__ lb,
                                   float* __restrict__ wcat, float* __restrict__ bcat)
{
    const int i = blockIdx.x * 256 + threadIdx.x;   // over 512*64
    if (i < 512 * 64) {
        const int k = i >> 6, c = i & 63;
        wcat[k * 128 + c]      = mw[i];
        wcat[k * 128 + 64 + c] = lw[i];
    }
    if (i < 64)  bcat[i] = mb[i];
    if (i >= 64 && i < 128) bcat[i] = lb[i - 64];
}

// ---------------------------------------------------------------------------
// 50-iteration continuous top-k; emits compact (idx, x*kh) for kh > 1e-5.
// Final cross-warp reductions done by warp 0 via shuffles.
// ---------------------------------------------------------------------------
__global__ __launch_bounds__(512)
void topk_kernel(const float* __restrict__ w_in, const float* __restrict__ noise,
                 const float* __restrict__ x,
                 float* __restrict__ spv, int* __restrict__ spi, int* __restrict__ spc)
{
    const int row = blockIdx.x;
    const int t = threadIdx.x;
    const size_t base = (size_t)row * 5000;
    const int lane = t & 31, wid = t >> 5;

    float wv[10], kh[10], e[10];
#pragma unroll
    for (int i = 0; i < 10; i++) {
        const int j = t + i * 512;
        kh[i] = 0.f;
        if (j < 5000) {
            float u = noise[base + j] + 1e-30f;
            wv[i] = w_in[base + j] + __logf(-__logf(u));
        } else {
            wv[i] = -3.0e38f;
        }
    }

    __shared__ float red[16];
    __shared__ float bc;
    __shared__ int s_cnt;
    if (t == 0) s_cnt = 0;

    for (int it = 0; it < 50; it++) {
        // ---- row max ----
        float m = wv[0];
#pragma unroll
        for (int i = 1; i < 10; i++) m = fmaxf(m, wv[i]);
#pragma unroll
        for (int o = 16; o > 0; o >>= 1) m = fmaxf(m, __shfl_xor_sync(0xffffffffu, m, o));
        if (lane == 0) red[wid] = m;
        __syncthreads();
        if (wid == 0) {
            float v = (lane < 16) ? red[lane] : -3.0e38f;
#pragma unroll
            for (int o = 8; o > 0; o >>= 1) v = fmaxf(v, __shfl_xor_sync(0xffffffffu, v, o));
            if (lane == 0) bc = v;
        }
        __syncthreads();
        m = bc;
        const float thresh = m - 3.0f;

        // ---- exp + row sum (gated) ----
        float s = 0.f;
#pragma unroll
        for (int i = 0; i < 10; i++) {
            e[i] = 0.f;
            if (__any_sync(0xffffffffu, wv[i] >= thresh)) {
                if (wv[i] >= thresh) {
                    float ee = __expf((wv[i] - m) * 10.0f);
                    e[i] = ee;
                    s += ee;
                }
            }
        }
#pragma unroll
        for (int o = 16; o > 0; o >>= 1) s += __shfl_xor_sync(0xffffffffu, s, o);
        if (lane == 0) red[wid] = s;
        __syncthreads();
        if (wid == 0) {
            float v = (lane < 16) ? red[lane] : 0.f;
#pragma unroll
            for (int o = 8; o > 0; o >>= 1) v += __shfl_xor_sync(0xffffffffu, v, o);
            if (lane == 0) bc = v;
        }
        __syncthreads();
        const float inv = 1.0f / bc;

        // ---- khot accumulate + suppression (gated) ----
#pragma unroll
        for (int i = 0; i < 10; i++) {
            if (__any_sync(0xffffffffu, e[i] > 0.f)) {
                if (e[i] > 0.f) {
                    float oh = e[i] * inv;
                    kh[i] += oh;
                    float mk = fmaxf(1.0f - oh, 1e-30f);
                    if (mk < 1.0f) wv[i] += __logf(mk);
                }
            }
        }
    }

    __syncthreads();
    const size_t sb = (size_t)row * SPCAP;
#pragma unroll
    for (int i = 0; i < 10; i++) {
        const int j = t + i * 512;
        if (j < 5000 && kh[i] > 1e-5f) {
            int p = atomicAdd(&s_cnt, 1);
            if (p < SPCAP) {
                spi[sb + p] = j;
                spv[sb + p] = x[base + j] * kh[i];
            }
        }
    }
    __syncthreads();
    if (t == 0) spc[row] = min(s_cnt, SPCAP);
}

// ---------------------------------------------------------------------------
// Sparse h1 = leaky(xm @ enc_w1 + b), unroll 8 for L2-latency MLP
// ---------------------------------------------------------------------------
__global__ __launch_bounds__(256)
void spmm_kernel(const float* __restrict__ spv, const int* __restrict__ spi,
                 const int* __restrict__ spc,
                 const float* __restrict__ W, const float* __restrict__ bias,
                 float* __restrict__ out)
{
    const int row = blockIdx.x;
    const int t = threadIdx.x;
    const int cnt = spc[row];
    const int col = t * 4;
    const size_t sb = (size_t)row * SPCAP;

    float ax = 0.f, ay = 0.f, az = 0.f, aw = 0.f;
    __shared__ float sv[256];
    __shared__ int   si[256];

    for (int s0 = 0; s0 < cnt; s0 += 256) {
        const int n = min(256, cnt - s0);
        if (t < n) { sv[t] = spv[sb + s0 + t]; si[t] = spi[sb + s0 + t]; }
        __syncthreads();
        int s = 0;
        for (; s + 8 <= n; s += 8) {
            float4 wr[8];
            float  vr[8];
#pragma unroll
            for (int q = 0; q < 8; q++) {
                wr[q] = *(const float4*)&W[(size_t)si[s + q] * 1024 + col];
                vr[q] = sv[s + q];
            }
#pragma unroll
            for (int q = 0; q < 8; q++) {
                ax = fmaf(vr[q], wr[q].x, ax);
                ay = fmaf(vr[q], wr[q].y, ay);
                az = fmaf(vr[q], wr[q].z, az);
                aw = fmaf(vr[q], wr[q].w, aw);
            }
        }
        for (; s < n; s++) {
            float4 w0 = *(const float4*)&W[(size_t)si[s] * 1024 + col];
            float v0 = sv[s];
            ax = fmaf(v0, w0.x, ax); ay = fmaf(v0, w0.y, ay);
            az = fmaf(v0, w0.z, az); aw = fmaf(v0, w0.w, aw);
        }
        __syncthreads();
    }

    float4 b4 = *(const float4*)&bias[col];
    float4 o;
    o.x = ax + b4.x; o.y = ay + b4.y; o.z = az + b4.z; o.w = aw + b4.w;
    o.x = o.x > 0.f ? o.x : 0.01f * o.x;
    o.y = o.y > 0.f ? o.y : 0.01f * o.y;
    o.z = o.z > 0.f ? o.z : 0.01f * o.z;
    o.w = o.w > 0.f ? o.w : 0.01f * o.w;
    *(float4*)&out[(size_t)row * 1024 + col] = o;
}

// ---------------------------------------------------------------------------
// split fused head + reparameterize:
// zcat[r][0:64]=mu, zcat[r][64:128]=logvar -> out_mu, out_lv, z
// ---------------------------------------------------------------------------
__global__ void reparam_split_kernel(const float* __restrict__ zcat,
                                     const float* __restrict__ eps,
                                     float* __restrict__ out_mu, float* __restrict__ out_lv,
                                     float* __restrict__ z)
{
    const int i = blockIdx.x * 256 + threadIdx.x;
    if (i < 4096 * 64) {
        const int r = i >> 6, c = i & 63;
        const float mu = zcat[(size_t)r * 128 + c];
        const float lv = zcat[(size_t)r * 128 + 64 + c];
        out_mu[i] = mu;
        out_lv[i] = lv;
        z[i] = fmaf(eps[i], __expf(0.5f * lv), mu);
    }
}

// ---------------------------------------------------------------------------
extern "C" void kernel_launch(void* const* d_in, const int* in_sizes, int n_in,
                              void* d_out, int out_size)
{
    const float* x     = (const float*)d_in[0];
    const float* noise = (const float*)d_in[1];
    const float* eps   = (const float*)d_in[2];
    const float* wc_w1 = (const float*)d_in[3];
    const float* wc_b1 = (const float*)d_in[4];
    const float* bn_g  = (const float*)d_in[5];
    const float* bn_b  = (const float*)d_in[6];
    const float* wc_w2 = (const float*)d_in[7];
    const float* wc_b2 = (const float*)d_in[8];
    const float* e_w1  = (const float*)d_in[9];
    const float* e_b1  = (const float*)d_in[10];
    const float* e_w2  = (const float*)d_in[11];
    const float* e_b2  = (const float*)d_in[12];
    const float* e_w3  = (const float*)d_in[13];
    const float* e_b3  = (const float*)d_in[14];
    const float* e_w4  = (const float*)d_in[15];
    const float* e_b4  = (const float*)d_in[16];
    const float* m_w   = (const float*)d_in[17];
    const float* m_b   = (const float*)d_in[18];
    const float* lvw   = (const float*)d_in[19];
    const float* lvb   = (const float*)d_in[20];
    const float* d_w1  = (const float*)d_in[21];
    const float* d_b1  = (const float*)d_in[22];
    const float* d_w2  = (const float*)d_in[23];
    const float* d_b2  = (const float*)d_in[24];

    float* out     = (float*)d_out;
    float* out_mux = out;
    float* out_mu  = out + (size_t)4096 * 5000;
    float* out_lv  = out_mu + (size_t)4096 * 64;

    float *h, *w, *h1, *h2, *h3, *z, *dh, *mean, *rstd, *spv, *wcat, *bcat, *zcat;
    int *spi, *spc;
    cudaGetSymbolAddress((void**)&h,    g_h);
    cudaGetSymbolAddress((void**)&w,    g_w);
    cudaGetSymbolAddress((void**)&h1,   g_h1);
    cudaGetSymbolAddress((void**)&h2,   g_h2);
    cudaGetSymbolAddress((void**)&h3,   g_h3);
    cudaGetSymbolAddress((void**)&z,    g_z);
    cudaGetSymbolAddress((void**)&dh,   g_dh);
    cudaGetSymbolAddress((void**)&mean, g_mean);
    cudaGetSymbolAddress((void**)&rstd, g_rstd);
    cudaGetSymbolAddress((void**)&spv,  g_spv);
    cudaGetSymbolAddress((void**)&spi,  g_spi);
    cudaGetSymbolAddress((void**)&spc,  g_spc);
    cudaGetSymbolAddress((void**)&wcat, g_wcat);
    cudaGetSymbolAddress((void**)&bcat, g_bcat);
    cudaGetSymbolAddress((void**)&zcat, g_zcat);

    cudaFuncSetAttribute((const void*)mma_gemm<EPI_NONE, 0>,    cudaFuncAttributeMaxDynamicSharedMemorySize, MMA_SMEM);
    cudaFuncSetAttribute((const void*)mma_gemm<EPI_NONE, 1>,    cudaFuncAttributeMaxDynamicSharedMemorySize, MMA_SMEM);
    cudaFuncSetAttribute((const void*)mma_gemm<EPI_LEAKY, 0>,   cudaFuncAttributeMaxDynamicSharedMemorySize, MMA_SMEM);
    cudaFuncSetAttribute((const void*)mma_gemm<EPI_SIGMOID, 0>, cudaFuncAttributeMaxDynamicSharedMemorySize, MMA_SMEM);

    const dim3 blk(256);
    auto grd = [](int N) { return dim3((N + 127) / 128, 32); };   // M = 4096 always
    const float* np = nullptr;

    // weight_creator
    mma_gemm<EPI_NONE, 0><<<grd(512), blk, MMA_SMEM>>>(x, wc_w1, wc_b1, h, 4096, 512, 5000, np, np, np, np);
    bn_stats_kernel<<<16, dim3(32, 8)>>>(h, mean, rstd);
    // wc_w2 with BN+ReLU fused into A staging
    mma_gemm<EPI_NONE, 1><<<grd(5000), blk, MMA_SMEM>>>(h, wc_w2, wc_b2, w, 4096, 5000, 512, mean, rstd, bn_g, bn_b);

    // gumbel + 50-step continuous top-k -> compact sparse xm
    topk_kernel<<<4096, 512>>>(w, noise, x, spv, spi, spc);

    // encoder (layer 1 sparse, rest tensor-core)
    spmm_kernel<<<4096, 256>>>(spv, spi, spc, e_w1, e_b1, h1);
    mma_gemm<EPI_LEAKY, 0><<<grd(512), blk, MMA_SMEM>>>(h1, e_w2, e_b2, h2, 4096, 512, 1024, np, np, np, np);
    mma_gemm<EPI_LEAKY, 0><<<grd(512), blk, MMA_SMEM>>>(h2, e_w3, e_b3, h3, 4096, 512, 512, np, np, np, np);
    mma_gemm<EPI_LEAKY, 0><<<grd(512), blk, MMA_SMEM>>>(h3, e_w4, e_b4, h, 4096, 512, 512, np, np, np, np);

    // fused mean/logvar head: one N=128 GEMM on concatenated weights
    concat_head_kernel<<<(512 * 64 + 255) / 256, 256>>>(m_w, lvw, m_b, lvb, wcat, bcat);
    mma_gemm<EPI_NONE, 0><<<grd(128), blk, MMA_SMEM>>>(h, wcat, bcat, zcat, 4096, 128, 512, np, np, np, np);

    // split + reparameterize + decoder
    reparam_split_kernel<<<(4096 * 64 + 255) / 256, 256>>>(zcat, eps, out_mu, out_lv, z);
    mma_gemm<EPI_LEAKY, 0><<<grd(1024), blk, MMA_SMEM>>>(z, d_w1, d_b1, dh, 4096, 1024, 64, np, np, np, np);
    mma_gemm<EPI_SIGMOID, 0><<<grd(5000), blk, MMA_SMEM>>>(dh, d_w2, d_b2, out_mux, 4096, 5000, 1024, np, np, np, np);
}